// round 12
// baseline (speedup 1.0000x reference)
#include <cuda_runtime.h>
#include <cuda_bf16.h>
#include <cstdint>

#define EPS 1e-15f

// ---------------- scratch buffers (no runtime allocation allowed) ----------
__device__ float g_qkv[(size_t)4 * 1536 * 4096];          // fp32 qkv
__device__ __nv_bfloat16 g_xt_h[(size_t)4 * 4096 * 512];  // x transposed, hi
__device__ __nv_bfloat16 g_xt_l[(size_t)4 * 4096 * 512];  // x transposed, lo
__device__ __nv_bfloat16 g_at_h[(size_t)4 * 4096 * 1024]; // attn transposed, hi
__device__ __nv_bfloat16 g_at_l[(size_t)4 * 4096 * 1024]; // attn transposed, lo
__device__ __nv_bfloat16 g_wq_h[1536 * 512];
__device__ __nv_bfloat16 g_wq_l[1536 * 512];
__device__ __nv_bfloat16 g_wp_h[512 * 1024];
__device__ __nv_bfloat16 g_wp_l[512 * 1024];

// ---------------- PTX helpers (base-target-safe: HMMA/ldmatrix/cp.async) ----
__device__ __forceinline__ uint32_t smem_u32(const void* p) {
  uint32_t a;
  asm("{ .reg .u64 t; cvta.to.shared.u64 t, %1; cvt.u32.u64 %0, t; }"
      : "=r"(a) : "l"(p));
  return a;
}

__device__ __forceinline__ void cp_async16(uint32_t saddr, const void* gptr) {
  asm volatile("cp.async.cg.shared.global [%0], [%1], 16;" ::
               "r"(saddr), "l"(gptr));
}
__device__ __forceinline__ void cp_commit() {
  asm volatile("cp.async.commit_group;");
}
__device__ __forceinline__ void cp_wait_all() {
  asm volatile("cp.async.wait_group 0;");
}

__device__ __forceinline__ void ldsm4(uint32_t* r, uint32_t addr) {
  asm volatile("ldmatrix.sync.aligned.m8n8.x4.shared.b16 {%0,%1,%2,%3}, [%4];"
               : "=r"(r[0]), "=r"(r[1]), "=r"(r[2]), "=r"(r[3]) : "r"(addr));
}

__device__ __forceinline__ void mma_bf16(float* d, const uint32_t* a,
                                         const uint32_t b0, const uint32_t b1) {
  asm volatile(
      "mma.sync.aligned.m16n8k16.row.col.f32.bf16.bf16.f32 "
      "{%0,%1,%2,%3}, {%4,%5,%6,%7}, {%8,%9}, {%0,%1,%2,%3};"
      : "+f"(d[0]), "+f"(d[1]), "+f"(d[2]), "+f"(d[3])
      : "r"(a[0]), "r"(a[1]), "r"(a[2]), "r"(a[3]), "r"(b0), "r"(b1));
}

// ---------------------------------------------------------------------------
// bf16x3 split GEMM on HMMA (mma.sync m16n8k16).  [Round-9 best config]
// ---------------------------------------------------------------------------
#define STAGE_BYTES 49152           // Ah 16K + Al 16K + Bh 8K + Bl 8K
#define GEMM_SMEM_BYTES (2 * STAGE_BYTES)

template <bool RES>
__global__ void __launch_bounds__(256, 2) gemm_hmma(
    const __nv_bfloat16* __restrict__ Ah, const __nv_bfloat16* __restrict__ Al,
    const __nv_bfloat16* __restrict__ Bh, const __nv_bfloat16* __restrict__ Bl,
    const float* __restrict__ Res, float* __restrict__ C, int M, int K) {
  extern __shared__ char smem[];
  const uint32_t sbase = smem_u32(smem);

  const int tid = threadIdx.x;
  const int warp = tid >> 5;
  const int lane = tid & 31;
  const int wm = warp >> 1;
  const int wn = warp & 1;
  const int m0 = blockIdx.x * 128;
  const int by = blockIdx.y;
  const int batch = by >> 6;
  const int n0 = (by & 63) * 64;
  const int NB = 4096;

  const __nv_bfloat16* Bhb = Bh + (size_t)batch * NB * K;
  const __nv_bfloat16* Blb = Bl + (size_t)batch * NB * K;

  float acc[2][4][4];
#pragma unroll
  for (int i = 0; i < 2; i++)
#pragma unroll
    for (int j = 0; j < 4; j++)
#pragma unroll
      for (int r = 0; r < 4; r++) acc[i][j][r] = 0.f;

  const int nch = K >> 6;

  const int lrow0 = tid >> 3;
  const int lc = tid & 7;
  auto load_stage = [&](int ch, int s) {
    const int k0 = ch << 6;
    const uint32_t sb = sbase + (uint32_t)s * STAGE_BYTES;
#pragma unroll
    for (int i = 0; i < 4; i++) {
      const int row = lrow0 + 32 * i;
      const uint32_t soff =
          (uint32_t)row * 128u + (uint32_t)((lc ^ (row & 7)) << 4);
      const size_t ga = (size_t)(m0 + row) * K + k0 + lc * 8;
      cp_async16(sb + 0u + soff, Ah + ga);
      cp_async16(sb + 16384u + soff, Al + ga);
    }
#pragma unroll
    for (int i = 0; i < 2; i++) {
      const int row = lrow0 + 32 * i;
      const uint32_t soff =
          (uint32_t)row * 128u + (uint32_t)((lc ^ (row & 7)) << 4);
      const size_t gb = (size_t)(n0 + row) * K + k0 + lc * 8;
      cp_async16(sb + 32768u + soff, Bhb + gb);
      cp_async16(sb + 40960u + soff, Blb + gb);
    }
    cp_commit();
  };

  load_stage(0, 0);

  const int lr = lane & 15;
  const int kh = lane >> 4;
  const int arow0 = wm * 32 + lr;
  const int brow0 = wn * 32 + lr;

  for (int ch = 0; ch < nch; ch++) {
    cp_wait_all();
    __syncthreads();
    if (ch + 1 < nch) load_stage(ch + 1, (ch + 1) & 1);

    const uint32_t sb = sbase + (uint32_t)(ch & 1) * STAGE_BYTES;
    const uint32_t sAh = sb, sAl = sb + 16384u;
    const uint32_t sBh = sb + 32768u, sBl = sb + 40960u;

    uint32_t ah[2][2][4], bh[2][2][4];
    uint32_t al[2][4], bl[2][4];

#pragma unroll
    for (int mt = 0; mt < 2; mt++) {
      const int row = arow0 + mt * 16;
      ldsm4(ah[0][mt],
            sAh + (uint32_t)row * 128u + (uint32_t)((kh ^ (row & 7)) << 4));
    }
#pragma unroll
    for (int nt2 = 0; nt2 < 2; nt2++) {
      const int row = brow0 + nt2 * 16;
      ldsm4(bh[0][nt2],
            sBh + (uint32_t)row * 128u + (uint32_t)((kh ^ (row & 7)) << 4));
    }

#pragma unroll
    for (int s = 0; s < 4; s++) {
      const int cur = s & 1, nxt = cur ^ 1;
      const int chunk = 2 * s + kh;
#pragma unroll
      for (int nt2 = 0; nt2 < 2; nt2++) {
        const int row = brow0 + nt2 * 16;
        ldsm4(bl[nt2], sBl + (uint32_t)row * 128u +
                           (uint32_t)((chunk ^ (row & 7)) << 4));
      }
#pragma unroll
      for (int mt = 0; mt < 2; mt++) {
        const int row = arow0 + mt * 16;
        ldsm4(al[mt], sAl + (uint32_t)row * 128u +
                          (uint32_t)((chunk ^ (row & 7)) << 4));
      }
#pragma unroll
      for (int mt = 0; mt < 2; mt++)
#pragma unroll
        for (int nt = 0; nt < 4; nt++)
          mma_bf16(acc[mt][nt], ah[cur][mt],
                   bh[cur][nt >> 1][nt & 1], bh[cur][nt >> 1][(nt & 1) + 2]);
      if (s < 3) {
        const int nchunk = chunk + 2;
#pragma unroll
        for (int mt = 0; mt < 2; mt++) {
          const int row = arow0 + mt * 16;
          ldsm4(ah[nxt][mt], sAh + (uint32_t)row * 128u +
                                 (uint32_t)((nchunk ^ (row & 7)) << 4));
        }
#pragma unroll
        for (int nt2 = 0; nt2 < 2; nt2++) {
          const int row = brow0 + nt2 * 16;
          ldsm4(bh[nxt][nt2], sBh + (uint32_t)row * 128u +
                                  (uint32_t)((nchunk ^ (row & 7)) << 4));
        }
      }
#pragma unroll
      for (int mt = 0; mt < 2; mt++)
#pragma unroll
        for (int nt = 0; nt < 4; nt++)
          mma_bf16(acc[mt][nt], ah[cur][mt],
                   bl[nt >> 1][nt & 1], bl[nt >> 1][(nt & 1) + 2]);
#pragma unroll
      for (int mt = 0; mt < 2; mt++)
#pragma unroll
        for (int nt = 0; nt < 4; nt++)
          mma_bf16(acc[mt][nt], al[mt],
                   bh[cur][nt >> 1][nt & 1], bh[cur][nt >> 1][(nt & 1) + 2]);
    }
  }

  const int qrow = lane >> 2;
  const int qcol = (lane & 3) * 2;
#pragma unroll
  for (int mt = 0; mt < 2; mt++) {
#pragma unroll
    for (int half = 0; half < 2; half++) {
      const int grow = m0 + wm * 32 + mt * 16 + qrow + half * 8;
      float* crow = C + ((size_t)batch * M + grow) * NB;
      const float* rrow =
          RES ? (Res + ((size_t)batch * M + grow) * NB) : nullptr;
#pragma unroll
      for (int nt = 0; nt < 4; nt++) {
        const int gcol = n0 + wn * 32 + nt * 8 + qcol;
        float2 v = make_float2(acc[mt][nt][half * 2],
                               acc[mt][nt][half * 2 + 1]);
        if (RES) {
          float2 r = *(const float2*)(rrow + gcol);
          v.x += r.x; v.y += r.y;
        }
        *(float2*)(crow + gcol) = v;
      }
    }
  }
}

// ---------------------------------------------------------------------------
// Split fp32 -> (bf16 hi, bf16 lo), elementwise (weights).
// ---------------------------------------------------------------------------
__global__ void split_bf16(const float* __restrict__ w,
                           __nv_bfloat16* __restrict__ h,
                           __nv_bfloat16* __restrict__ l, int n) {
  int i = blockIdx.x * blockDim.x + threadIdx.x;
  if (i < n) {
    float v = w[i];
    __nv_bfloat16 hi = __float2bfloat16(v);
    h[i] = hi;
    l[i] = __float2bfloat16(v - __bfloat162float(hi));
  }
}

// ---------------------------------------------------------------------------
// Transpose [B][K][4096] fp32 -> [B][4096][K] bf16 hi/lo split.
// ---------------------------------------------------------------------------
__global__ void transpose_split(const float* __restrict__ X,
                                __nv_bfloat16* __restrict__ Th,
                                __nv_bfloat16* __restrict__ Tl, int K) {
  __shared__ float t[32][33];
  const int nb = blockIdx.x * 32, kb = blockIdx.y * 32, b = blockIdx.z;
  const int tx = threadIdx.x, ty = threadIdx.y;
  const float* Xb = X + (size_t)b * K * 4096;
#pragma unroll
  for (int j = 0; j < 4; j++)
    t[ty + 8 * j][tx] = Xb[(size_t)(kb + ty + 8 * j) * 4096 + nb + tx];
  __syncthreads();
#pragma unroll
  for (int j = 0; j < 4; j++) {
    float v = t[tx][ty + 8 * j];
    const int n = nb + ty + 8 * j;
    const int k = kb + tx;
    __nv_bfloat16 hi = __float2bfloat16(v);
    const size_t o = ((size_t)b * 4096 + n) * K + k;
    Th[o] = hi;
    Tl[o] = __float2bfloat16(v - __bfloat162float(hi));
  }
}

// ---------------------------------------------------------------------------
// Helper: emit transposed bf16 hi/lo attention output for one pixel.
// ---------------------------------------------------------------------------
__device__ __forceinline__ void attn_emit(
    const float* vk, const float* qv, int b, int n, int hout,
    __nv_bfloat16* oth, __nv_bfloat16* otl) {
  float den = EPS;
#pragma unroll
  for (int e = 0; e < 8; e++) den += vk[64 + e] * qv[e];
  float rden = 1.0f / den;
  unsigned short hh[8], ll[8];
#pragma unroll
  for (int d = 0; d < 8; d++) {
    float num = 0.f;
#pragma unroll
    for (int e = 0; e < 8; e++) num += vk[d * 8 + e] * qv[e];
    float v = num * rden;
    __nv_bfloat16 hb = __float2bfloat16(v);
    hh[d] = __bfloat16_as_ushort(hb);
    ll[d] = __bfloat16_as_ushort(__float2bfloat16(v - __bfloat162float(hb)));
  }
  const size_t o = ((size_t)b * 4096 + n) * 1024 + (size_t)hout * 8;
  uint4 uh, ul;
  uh.x = (uint32_t)hh[0] | ((uint32_t)hh[1] << 16);
  uh.y = (uint32_t)hh[2] | ((uint32_t)hh[3] << 16);
  uh.z = (uint32_t)hh[4] | ((uint32_t)hh[5] << 16);
  uh.w = (uint32_t)hh[6] | ((uint32_t)hh[7] << 16);
  ul.x = (uint32_t)ll[0] | ((uint32_t)ll[1] << 16);
  ul.y = (uint32_t)ll[2] | ((uint32_t)ll[3] << 16);
  ul.z = (uint32_t)ll[4] | ((uint32_t)ll[5] << 16);
  ul.w = (uint32_t)ll[6] | ((uint32_t)ll[7] << 16);
  *(uint4*)(oth + o) = uh;
  *(uint4*)(otl + o) = ul;
}

// ---------------------------------------------------------------------------
// Block-wide reduction of per-thread a[72] into smem svk[72].
// ---------------------------------------------------------------------------
__device__ __forceinline__ void reduce72(float* a, float* svk, int tid) {
#pragma unroll
  for (int t = 0; t < 72; t++) {
    float s = a[t];
    s += __shfl_down_sync(0xffffffffu, s, 16);
    s += __shfl_down_sync(0xffffffffu, s, 8);
    s += __shfl_down_sync(0xffffffffu, s, 4);
    s += __shfl_down_sync(0xffffffffu, s, 2);
    s += __shfl_down_sync(0xffffffffu, s, 1);
    if ((tid & 31) == 0) atomicAdd(&svk[t], s);
  }
}

// ---------------------------------------------------------------------------
// Linear attention for heads 0..63 (reads qkv directly). 256 blocks.
// ---------------------------------------------------------------------------
__global__ __launch_bounds__(256) void attn_qkv_kernel(
    const float* __restrict__ qkv,
    __nv_bfloat16* __restrict__ oth, __nv_bfloat16* __restrict__ otl) {
  const int bh = blockIdx.x;
  const int b = bh >> 6;
  const int h = bh & 63;
  const float* base = qkv + (size_t)(b * 1536 + h * 24) * 4096;
  const float4* qp4 = (const float4*)base;
  const float4* kp4 = (const float4*)(base + (size_t)8 * 4096);
  const float4* vp4 = (const float4*)(base + (size_t)16 * 4096);

  __shared__ float svk[72];
  const int tid = threadIdx.x;
  if (tid < 72) svk[tid] = 0.f;
  __syncthreads();

  float a[72];
#pragma unroll
  for (int t = 0; t < 72; t++) a[t] = 0.f;

  for (int n4 = tid; n4 < 1024; n4 += 256) {
    float4 kv4[8], vv4[8];
#pragma unroll
    for (int e = 0; e < 8; e++) {
      float4 f = kp4[e * 1024 + n4];
      kv4[e] = make_float4(fmaxf(f.x, 0.f), fmaxf(f.y, 0.f),
                           fmaxf(f.z, 0.f), fmaxf(f.w, 0.f));
    }
#pragma unroll
    for (int d = 0; d < 8; d++) vv4[d] = vp4[d * 1024 + n4];
#pragma unroll
    for (int d = 0; d < 8; d++)
#pragma unroll
      for (int e = 0; e < 8; e++)
        a[d * 8 + e] += vv4[d].x * kv4[e].x + vv4[d].y * kv4[e].y +
                        vv4[d].z * kv4[e].z + vv4[d].w * kv4[e].w;
#pragma unroll
    for (int e = 0; e < 8; e++)
      a[64 + e] += kv4[e].x + kv4[e].y + kv4[e].z + kv4[e].w;
  }

  reduce72(a, svk, tid);
  __syncthreads();

  float vk[72];
#pragma unroll
  for (int t = 0; t < 72; t++) vk[t] = svk[t];

  for (int n4 = tid; n4 < 1024; n4 += 256) {
    float qs[4][8];
#pragma unroll
    for (int e = 0; e < 8; e++) {
      float4 f = qp4[e * 1024 + n4];
      qs[0][e] = fmaxf(f.x, 0.f);
      qs[1][e] = fmaxf(f.y, 0.f);
      qs[2][e] = fmaxf(f.z, 0.f);
      qs[3][e] = fmaxf(f.w, 0.f);
    }
#pragma unroll
    for (int sub = 0; sub < 4; sub++)
      attn_emit(vk, qs[sub], b, n4 * 4 + sub, h, oth, otl);
  }
}

// ---------------------------------------------------------------------------
// FUSED dwpw + linear attention for heads 64..127.
// One block per (b, h'). agg never touches HBM: the 24 channels of this head
// (= pw groups 3h', 3h'+1, 3h'+2) are computed from qkv on the fly per
// 8-row strip; k,v feed the vk accumulator immediately, relu(q) is stashed
// in smem (fp32) for phase 2.
// smem layout (floats):
//   tile   [24][12][68]  @ 0       (19584)
//   qstash [8][4096]     @ 19584   (32768)
//   wd     [24][25]      @ 52352   (600)
//   wp     [24][8]       @ 52952   (192)
//   svk    [72]          @ 53144   (72)
// total 53216 floats = 212,864 bytes
// ---------------------------------------------------------------------------
#define FUSED_SMEM_BYTES (53216 * 4)

__global__ __launch_bounds__(256, 1) void attn_fused_kernel(
    const float* __restrict__ qkv, const float* __restrict__ w_dw,
    const float* __restrict__ w_pw,
    __nv_bfloat16* __restrict__ oth, __nv_bfloat16* __restrict__ otl) {
  extern __shared__ float sm[];
  float* tile = sm;                 // [24][12][68]
  float* qstash = sm + 19584;       // [8][4096]
  float* wd = sm + 52352;           // [24][25]
  float* wp = sm + 52952;           // [24][8]
  float* svk = sm + 53144;          // [72]

  const int tid = threadIdx.x;
  const int bh = blockIdx.x;        // 256
  const int b = bh >> 6;
  const int hp = bh & 63;           // h' = h - 64
  const float* src = qkv + (size_t)(b * 1536 + hp * 24) * 4096;

  for (int t = tid; t < 600; t += 256) wd[t] = w_dw[(size_t)(hp * 24) * 25 + t];
  for (int t = tid; t < 192; t += 256) wp[t] = w_pw[(size_t)(hp * 24) * 8 + t];
  if (tid < 72) svk[tid] = 0.f;
  __syncthreads();

  float a[72];
#pragma unroll
  for (int t = 0; t < 72; t++) a[t] = 0.f;

  const int px = tid & 63;
  const int seg = tid >> 6;          // 0..3
  const int py0 = seg * 2;           // strip-local output rows py0, py0+1

  for (int strip = 0; strip < 8; strip++) {
    const int r0 = strip * 8;
    // load tile: 24 ch x 12 rows x 68 cols (zero halo)
    for (int e = tid; e < 24 * 12 * 68; e += 256) {
      int i = e / 816;
      int rem = e - i * 816;
      int ry = rem / 68;
      int rx = rem - ry * 68;
      int gy = r0 + ry - 2;
      int gx = rx - 2;
      float v = 0.f;
      if (gy >= 0 && gy < 64 && gx >= 0 && gx < 64)
        v = src[(size_t)i * 4096 + gy * 64 + gx];
      tile[i * 816 + ry * 68 + rx] = v;
    }
    __syncthreads();

    float kvv[2][8], vvv[2][8];
#pragma unroll
    for (int grp = 0; grp < 3; grp++) {
      float dwv[2][8];
#pragma unroll
      for (int i = 0; i < 8; i++) {
        const int ch = grp * 8 + i;
        const float* wdi = wd + ch * 25;
        const float* trow = tile + ch * 816 + py0 * 68 + px;
        float s0 = 0.f, s1 = 0.f;
#pragma unroll
        for (int r = 0; r < 6; r++) {
          float w0 = trow[r * 68 + 0];
          float w1 = trow[r * 68 + 1];
          float w2 = trow[r * 68 + 2];
          float w3 = trow[r * 68 + 3];
          float w4 = trow[r * 68 + 4];
          if (r < 5) {
            const float* wk = wdi + r * 5;
            s0 += w0 * wk[0] + w1 * wk[1] + w2 * wk[2] + w3 * wk[3] +
                  w4 * wk[4];
          }
          if (r >= 1) {
            const float* wk = wdi + (r - 1) * 5;
            s1 += w0 * wk[0] + w1 * wk[1] + w2 * wk[2] + w3 * wk[3] +
                  w4 * wk[4];
          }
        }
        dwv[0][i] = s0;
        dwv[1][i] = s1;
      }
      // pointwise 8x8 for this group
#pragma unroll
      for (int p = 0; p < 2; p++) {
#pragma unroll
        for (int o = 0; o < 8; o++) {
          const float* wpo = wp + (grp * 8 + o) * 8;
          float v = 0.f;
#pragma unroll
          for (int i = 0; i < 8; i++) v += wpo[i] * dwv[p][i];
          if (grp == 0) {
            qstash[o * 4096 + (r0 + py0 + p) * 64 + px] = fmaxf(v, 0.f);
          } else if (grp == 1) {
            kvv[p][o] = fmaxf(v, 0.f);
          } else {
            vvv[p][o] = v;
          }
        }
      }
    }
    // vk accumulation for this strip's 2 pixels
#pragma unroll
    for (int p = 0; p < 2; p++) {
#pragma unroll
      for (int d = 0; d < 8; d++)
#pragma unroll
        for (int e = 0; e < 8; e++) a[d * 8 + e] += vvv[p][d] * kvv[p][e];
#pragma unroll
      for (int e = 0; e < 8; e++) a[64 + e] += kvv[p][e];
    }
    __syncthreads();   // protect tile before next strip's overwrite
  }

  reduce72(a, svk, tid);
  __syncthreads();

  float vk[72];
#pragma unroll
  for (int t = 0; t < 72; t++) vk[t] = svk[t];

  // phase 2: q already relu'd in qstash (fp32)
  for (int n = tid; n < 4096; n += 256) {
    float qv[8];
#pragma unroll
    for (int e = 0; e < 8; e++) qv[e] = qstash[e * 4096 + n];
    attn_emit(vk, qv, b, n, hp + 64, oth, otl);
  }
}

// ---------------------------------------------------------------------------
extern "C" void kernel_launch(void* const* d_in, const int* in_sizes, int n_in,
                              void* d_out, int out_size) {
  const float* x      = (const float*)d_in[0];
  const float* w_qkv  = (const float*)d_in[1];
  const float* w_dw   = (const float*)d_in[2];
  const float* w_pw   = (const float*)d_in[3];
  const float* w_proj = (const float*)d_in[4];
  float* out = (float*)d_out;

  float* qkv;
  __nv_bfloat16 *xth, *xtl, *ath, *atl, *wqh, *wql, *wph, *wpl;
  cudaGetSymbolAddress((void**)&qkv, g_qkv);
  cudaGetSymbolAddress((void**)&xth, g_xt_h);
  cudaGetSymbolAddress((void**)&xtl, g_xt_l);
  cudaGetSymbolAddress((void**)&ath, g_at_h);
  cudaGetSymbolAddress((void**)&atl, g_at_l);
  cudaGetSymbolAddress((void**)&wqh, g_wq_h);
  cudaGetSymbolAddress((void**)&wql, g_wq_l);
  cudaGetSymbolAddress((void**)&wph, g_wp_h);
  cudaGetSymbolAddress((void**)&wpl, g_wp_l);

  cudaFuncSetAttribute(gemm_hmma<false>,
                       cudaFuncAttributeMaxDynamicSharedMemorySize,
                       GEMM_SMEM_BYTES);
  cudaFuncSetAttribute(gemm_hmma<true>,
                       cudaFuncAttributeMaxDynamicSharedMemorySize,
                       GEMM_SMEM_BYTES);
  cudaFuncSetAttribute(attn_fused_kernel,
                       cudaFuncAttributeMaxDynamicSharedMemorySize,
                       FUSED_SMEM_BYTES);

  // weight splits (tiny)
  split_bf16<<<(1536 * 512 + 255) / 256, 256>>>(w_qkv, wqh, wql, 1536 * 512);
  split_bf16<<<(512 * 1024 + 255) / 256, 256>>>(w_proj, wph, wpl, 512 * 1024);
  // x -> transposed bf16 split
  transpose_split<<<dim3(128, 16, 4), dim3(32, 8)>>>(x, xth, xtl, 512);
  // 1) qkv = w_qkv @ x  (HMMA bf16x3)
  gemm_hmma<false><<<dim3(12, 256), 256, GEMM_SMEM_BYTES>>>(
      wqh, wql, xth, xtl, nullptr, qkv, 1536, 512);
  // 2) fused dwpw+attention for agg heads (64..127) — agg never hits HBM
  attn_fused_kernel<<<256, 256, FUSED_SMEM_BYTES>>>(qkv, w_dw, w_pw, ath, atl);
  // 3) attention for qkv heads (0..63)
  attn_qkv_kernel<<<256, 256>>>(qkv, ath, atl);
  // 4) out = x + w_proj @ attn  (HMMA bf16x3 + residual)
  gemm_hmma<true><<<dim3(4, 256), 256, GEMM_SMEM_BYTES>>>(
      wph, wpl, ath, atl, x, out, 512, 1024);
}

// round 13
// speedup vs baseline: 1.2747x; 1.2747x over previous
#include <cuda_runtime.h>
#include <cuda_bf16.h>
#include <cstdint>

#define EPS 1e-15f

// ---------------- scratch buffers (no runtime allocation allowed) ----------
__device__ float g_qkv[(size_t)4 * 1536 * 4096];          // fp32 qkv
__device__ float g_agg[(size_t)4 * 1536 * 4096];          // fp32 agg
__device__ __nv_bfloat16 g_xt_h[(size_t)4 * 4096 * 512];  // x transposed, hi
__device__ __nv_bfloat16 g_xt_l[(size_t)4 * 4096 * 512];  // x transposed, lo
__device__ __nv_bfloat16 g_at_h[(size_t)4 * 4096 * 1024]; // attn transposed, hi
__device__ __nv_bfloat16 g_at_l[(size_t)4 * 4096 * 1024]; // attn transposed, lo
__device__ __nv_bfloat16 g_wq_h[1536 * 512];
__device__ __nv_bfloat16 g_wq_l[1536 * 512];
__device__ __nv_bfloat16 g_wp_h[512 * 1024];
__device__ __nv_bfloat16 g_wp_l[512 * 1024];

// ---------------- PTX helpers (base-target-safe: HMMA/ldmatrix/cp.async) ----
__device__ __forceinline__ uint32_t smem_u32(const void* p) {
  uint32_t a;
  asm("{ .reg .u64 t; cvta.to.shared.u64 t, %1; cvt.u32.u64 %0, t; }"
      : "=r"(a) : "l"(p));
  return a;
}

__device__ __forceinline__ void cp_async16(uint32_t saddr, const void* gptr) {
  asm volatile("cp.async.cg.shared.global [%0], [%1], 16;" ::
               "r"(saddr), "l"(gptr));
}
__device__ __forceinline__ void cp_commit() {
  asm volatile("cp.async.commit_group;");
}
__device__ __forceinline__ void cp_wait_all() {
  asm volatile("cp.async.wait_group 0;");
}

__device__ __forceinline__ void ldsm4(uint32_t* r, uint32_t addr) {
  asm volatile("ldmatrix.sync.aligned.m8n8.x4.shared.b16 {%0,%1,%2,%3}, [%4];"
               : "=r"(r[0]), "=r"(r[1]), "=r"(r[2]), "=r"(r[3]) : "r"(addr));
}

__device__ __forceinline__ void mma_bf16(float* d, const uint32_t* a,
                                         const uint32_t b0, const uint32_t b1) {
  asm volatile(
      "mma.sync.aligned.m16n8k16.row.col.f32.bf16.bf16.f32 "
      "{%0,%1,%2,%3}, {%4,%5,%6,%7}, {%8,%9}, {%0,%1,%2,%3};"
      : "+f"(d[0]), "+f"(d[1]), "+f"(d[2]), "+f"(d[3])
      : "r"(a[0]), "r"(a[1]), "r"(a[2]), "r"(a[3]), "r"(b0), "r"(b1));
}

// ---------------------------------------------------------------------------
// bf16x3 split GEMM on HMMA (mma.sync m16n8k16).  [Round-9 best config]
// ---------------------------------------------------------------------------
#define STAGE_BYTES 49152           // Ah 16K + Al 16K + Bh 8K + Bl 8K
#define GEMM_SMEM_BYTES (2 * STAGE_BYTES)

template <bool RES>
__global__ void __launch_bounds__(256, 2) gemm_hmma(
    const __nv_bfloat16* __restrict__ Ah, const __nv_bfloat16* __restrict__ Al,
    const __nv_bfloat16* __restrict__ Bh, const __nv_bfloat16* __restrict__ Bl,
    const float* __restrict__ Res, float* __restrict__ C, int M, int K) {
  extern __shared__ char smem[];
  const uint32_t sbase = smem_u32(smem);

  const int tid = threadIdx.x;
  const int warp = tid >> 5;
  const int lane = tid & 31;
  const int wm = warp >> 1;
  const int wn = warp & 1;
  const int m0 = blockIdx.x * 128;
  const int by = blockIdx.y;
  const int batch = by >> 6;
  const int n0 = (by & 63) * 64;
  const int NB = 4096;

  const __nv_bfloat16* Bhb = Bh + (size_t)batch * NB * K;
  const __nv_bfloat16* Blb = Bl + (size_t)batch * NB * K;

  float acc[2][4][4];
#pragma unroll
  for (int i = 0; i < 2; i++)
#pragma unroll
    for (int j = 0; j < 4; j++)
#pragma unroll
      for (int r = 0; r < 4; r++) acc[i][j][r] = 0.f;

  const int nch = K >> 6;

  const int lrow0 = tid >> 3;
  const int lc = tid & 7;
  auto load_stage = [&](int ch, int s) {
    const int k0 = ch << 6;
    const uint32_t sb = sbase + (uint32_t)s * STAGE_BYTES;
#pragma unroll
    for (int i = 0; i < 4; i++) {
      const int row = lrow0 + 32 * i;
      const uint32_t soff =
          (uint32_t)row * 128u + (uint32_t)((lc ^ (row & 7)) << 4);
      const size_t ga = (size_t)(m0 + row) * K + k0 + lc * 8;
      cp_async16(sb + 0u + soff, Ah + ga);
      cp_async16(sb + 16384u + soff, Al + ga);
    }
#pragma unroll
    for (int i = 0; i < 2; i++) {
      const int row = lrow0 + 32 * i;
      const uint32_t soff =
          (uint32_t)row * 128u + (uint32_t)((lc ^ (row & 7)) << 4);
      const size_t gb = (size_t)(n0 + row) * K + k0 + lc * 8;
      cp_async16(sb + 32768u + soff, Bhb + gb);
      cp_async16(sb + 40960u + soff, Blb + gb);
    }
    cp_commit();
  };

  load_stage(0, 0);

  const int lr = lane & 15;
  const int kh = lane >> 4;
  const int arow0 = wm * 32 + lr;
  const int brow0 = wn * 32 + lr;

  for (int ch = 0; ch < nch; ch++) {
    cp_wait_all();
    __syncthreads();
    if (ch + 1 < nch) load_stage(ch + 1, (ch + 1) & 1);

    const uint32_t sb = sbase + (uint32_t)(ch & 1) * STAGE_BYTES;
    const uint32_t sAh = sb, sAl = sb + 16384u;
    const uint32_t sBh = sb + 32768u, sBl = sb + 40960u;

    uint32_t ah[2][2][4], bh[2][2][4];
    uint32_t al[2][4], bl[2][4];

#pragma unroll
    for (int mt = 0; mt < 2; mt++) {
      const int row = arow0 + mt * 16;
      ldsm4(ah[0][mt],
            sAh + (uint32_t)row * 128u + (uint32_t)((kh ^ (row & 7)) << 4));
    }
#pragma unroll
    for (int nt2 = 0; nt2 < 2; nt2++) {
      const int row = brow0 + nt2 * 16;
      ldsm4(bh[0][nt2],
            sBh + (uint32_t)row * 128u + (uint32_t)((kh ^ (row & 7)) << 4));
    }

#pragma unroll
    for (int s = 0; s < 4; s++) {
      const int cur = s & 1, nxt = cur ^ 1;
      const int chunk = 2 * s + kh;
#pragma unroll
      for (int nt2 = 0; nt2 < 2; nt2++) {
        const int row = brow0 + nt2 * 16;
        ldsm4(bl[nt2], sBl + (uint32_t)row * 128u +
                           (uint32_t)((chunk ^ (row & 7)) << 4));
      }
#pragma unroll
      for (int mt = 0; mt < 2; mt++) {
        const int row = arow0 + mt * 16;
        ldsm4(al[mt], sAl + (uint32_t)row * 128u +
                          (uint32_t)((chunk ^ (row & 7)) << 4));
      }
#pragma unroll
      for (int mt = 0; mt < 2; mt++)
#pragma unroll
        for (int nt = 0; nt < 4; nt++)
          mma_bf16(acc[mt][nt], ah[cur][mt],
                   bh[cur][nt >> 1][nt & 1], bh[cur][nt >> 1][(nt & 1) + 2]);
      if (s < 3) {
        const int nchunk = chunk + 2;
#pragma unroll
        for (int mt = 0; mt < 2; mt++) {
          const int row = arow0 + mt * 16;
          ldsm4(ah[nxt][mt], sAh + (uint32_t)row * 128u +
                                 (uint32_t)((nchunk ^ (row & 7)) << 4));
        }
#pragma unroll
        for (int nt2 = 0; nt2 < 2; nt2++) {
          const int row = brow0 + nt2 * 16;
          ldsm4(bh[nxt][nt2], sBh + (uint32_t)row * 128u +
                                  (uint32_t)((nchunk ^ (row & 7)) << 4));
        }
      }
#pragma unroll
      for (int mt = 0; mt < 2; mt++)
#pragma unroll
        for (int nt = 0; nt < 4; nt++)
          mma_bf16(acc[mt][nt], ah[cur][mt],
                   bl[nt >> 1][nt & 1], bl[nt >> 1][(nt & 1) + 2]);
#pragma unroll
      for (int mt = 0; mt < 2; mt++)
#pragma unroll
        for (int nt = 0; nt < 4; nt++)
          mma_bf16(acc[mt][nt], al[mt],
                   bh[cur][nt >> 1][nt & 1], bh[cur][nt >> 1][(nt & 1) + 2]);
    }
  }

  const int qrow = lane >> 2;
  const int qcol = (lane & 3) * 2;
#pragma unroll
  for (int mt = 0; mt < 2; mt++) {
#pragma unroll
    for (int half = 0; half < 2; half++) {
      const int grow = m0 + wm * 32 + mt * 16 + qrow + half * 8;
      float* crow = C + ((size_t)batch * M + grow) * NB;
      const float* rrow =
          RES ? (Res + ((size_t)batch * M + grow) * NB) : nullptr;
#pragma unroll
      for (int nt = 0; nt < 4; nt++) {
        const int gcol = n0 + wn * 32 + nt * 8 + qcol;
        float2 v = make_float2(acc[mt][nt][half * 2],
                               acc[mt][nt][half * 2 + 1]);
        if (RES) {
          float2 r = *(const float2*)(rrow + gcol);
          v.x += r.x; v.y += r.y;
        }
        *(float2*)(crow + gcol) = v;
      }
    }
  }
}

// ---------------------------------------------------------------------------
// Split fp32 -> (bf16 hi, bf16 lo), elementwise (weights).
// ---------------------------------------------------------------------------
__global__ void split_bf16(const float* __restrict__ w,
                           __nv_bfloat16* __restrict__ h,
                           __nv_bfloat16* __restrict__ l, int n) {
  int i = blockIdx.x * blockDim.x + threadIdx.x;
  if (i < n) {
    float v = w[i];
    __nv_bfloat16 hi = __float2bfloat16(v);
    h[i] = hi;
    l[i] = __float2bfloat16(v - __bfloat162float(hi));
  }
}

// ---------------------------------------------------------------------------
// Transpose [B][K][4096] fp32 -> [B][4096][K] bf16 hi/lo split.
// ---------------------------------------------------------------------------
__global__ void transpose_split(const float* __restrict__ X,
                                __nv_bfloat16* __restrict__ Th,
                                __nv_bfloat16* __restrict__ Tl, int K) {
  __shared__ float t[32][33];
  const int nb = blockIdx.x * 32, kb = blockIdx.y * 32, b = blockIdx.z;
  const int tx = threadIdx.x, ty = threadIdx.y;
  const float* Xb = X + (size_t)b * K * 4096;
#pragma unroll
  for (int j = 0; j < 4; j++)
    t[ty + 8 * j][tx] = Xb[(size_t)(kb + ty + 8 * j) * 4096 + nb + tx];
  __syncthreads();
#pragma unroll
  for (int j = 0; j < 4; j++) {
    float v = t[tx][ty + 8 * j];
    const int n = nb + ty + 8 * j;
    const int k = kb + tx;
    __nv_bfloat16 hi = __float2bfloat16(v);
    const size_t o = ((size_t)b * 4096 + n) * K + k;
    Th[o] = hi;
    Tl[o] = __float2bfloat16(v - __bfloat162float(hi));
  }
}

// ---------------------------------------------------------------------------
// Helper: emit transposed bf16 hi/lo attention output for one pixel.
// ---------------------------------------------------------------------------
__device__ __forceinline__ void attn_emit(
    const float* vk, const float* qv, int b, int n, int hout,
    __nv_bfloat16* oth, __nv_bfloat16* otl) {
  float den = EPS;
#pragma unroll
  for (int e = 0; e < 8; e++) den += vk[64 + e] * qv[e];
  float rden = 1.0f / den;
  unsigned short hh[8], ll[8];
#pragma unroll
  for (int d = 0; d < 8; d++) {
    float num = 0.f;
#pragma unroll
    for (int e = 0; e < 8; e++) num += vk[d * 8 + e] * qv[e];
    float v = num * rden;
    __nv_bfloat16 hb = __float2bfloat16(v);
    hh[d] = __bfloat16_as_ushort(hb);
    ll[d] = __bfloat16_as_ushort(__float2bfloat16(v - __bfloat162float(hb)));
  }
  const size_t o = ((size_t)b * 4096 + n) * 1024 + (size_t)hout * 8;
  uint4 uh, ul;
  uh.x = (uint32_t)hh[0] | ((uint32_t)hh[1] << 16);
  uh.y = (uint32_t)hh[2] | ((uint32_t)hh[3] << 16);
  uh.z = (uint32_t)hh[4] | ((uint32_t)hh[5] << 16);
  uh.w = (uint32_t)hh[6] | ((uint32_t)hh[7] << 16);
  ul.x = (uint32_t)ll[0] | ((uint32_t)ll[1] << 16);
  ul.y = (uint32_t)ll[2] | ((uint32_t)ll[3] << 16);
  ul.z = (uint32_t)ll[4] | ((uint32_t)ll[5] << 16);
  ul.w = (uint32_t)ll[6] | ((uint32_t)ll[7] << 16);
  *(uint4*)(oth + o) = uh;
  *(uint4*)(otl + o) = ul;
}

__device__ __forceinline__ void reduce72(float* a, float* svk, int tid) {
#pragma unroll
  for (int t = 0; t < 72; t++) {
    float s = a[t];
    s += __shfl_down_sync(0xffffffffu, s, 16);
    s += __shfl_down_sync(0xffffffffu, s, 8);
    s += __shfl_down_sync(0xffffffffu, s, 4);
    s += __shfl_down_sync(0xffffffffu, s, 2);
    s += __shfl_down_sync(0xffffffffu, s, 1);
    if ((tid & 31) == 0) atomicAdd(&svk[t], s);
  }
}

// ---------------------------------------------------------------------------
// Full linear-attention block body for one head located at `base`
// (24 channel planes of 4096), output head index hout. Uses smem svk[72].
// ---------------------------------------------------------------------------
__device__ __forceinline__ void attn_head_body(
    const float* base, int b, int hout, float* svk,
    __nv_bfloat16* oth, __nv_bfloat16* otl) {
  const float4* qp4 = (const float4*)base;
  const float4* kp4 = (const float4*)(base + (size_t)8 * 4096);
  const float4* vp4 = (const float4*)(base + (size_t)16 * 4096);

  const int tid = threadIdx.x;
  if (tid < 72) svk[tid] = 0.f;
  __syncthreads();

  float a[72];
#pragma unroll
  for (int t = 0; t < 72; t++) a[t] = 0.f;

  for (int n4 = tid; n4 < 1024; n4 += 256) {
    float4 kv4[8], vv4[8];
#pragma unroll
    for (int e = 0; e < 8; e++) {
      float4 f = kp4[e * 1024 + n4];
      kv4[e] = make_float4(fmaxf(f.x, 0.f), fmaxf(f.y, 0.f),
                           fmaxf(f.z, 0.f), fmaxf(f.w, 0.f));
    }
#pragma unroll
    for (int d = 0; d < 8; d++) vv4[d] = vp4[d * 1024 + n4];
#pragma unroll
    for (int d = 0; d < 8; d++)
#pragma unroll
      for (int e = 0; e < 8; e++)
        a[d * 8 + e] += vv4[d].x * kv4[e].x + vv4[d].y * kv4[e].y +
                        vv4[d].z * kv4[e].z + vv4[d].w * kv4[e].w;
#pragma unroll
    for (int e = 0; e < 8; e++)
      a[64 + e] += kv4[e].x + kv4[e].y + kv4[e].z + kv4[e].w;
  }

  reduce72(a, svk, tid);
  __syncthreads();

  float vk[72];
#pragma unroll
  for (int t = 0; t < 72; t++) vk[t] = svk[t];

  for (int n4 = tid; n4 < 1024; n4 += 256) {
    float qs[4][8];
#pragma unroll
    for (int e = 0; e < 8; e++) {
      float4 f = qp4[e * 1024 + n4];
      qs[0][e] = fmaxf(f.x, 0.f);
      qs[1][e] = fmaxf(f.y, 0.f);
      qs[2][e] = fmaxf(f.z, 0.f);
      qs[3][e] = fmaxf(f.w, 0.f);
    }
#pragma unroll
    for (int sub = 0; sub < 4; sub++)
      attn_emit(vk, qs[sub], b, n4 * 4 + sub, hout, oth, otl);
  }
}

// ---------------------------------------------------------------------------
// MERGED kernel: blocks 0..255 run attention for qkv heads 0..63 (reads only
// qkv); blocks 256..3327 run dwpw conv tiles (write agg). The two roles are
// independent; merging overlaps DRAM-bound attention with LDS-bound conv.
// Dynamic smem (44,576 B) partition for dwpw:
//   tile [8][20][68] @0 (10880 f) | wd [8][25] @10880 | wp[64] @11080
// attention role uses only svk = first 72 floats.
// ---------------------------------------------------------------------------
#define MERGED_SMEM_BYTES (11144 * 4)

__global__ __launch_bounds__(256) void dwpw_attnq_kernel(
    const float* __restrict__ qkv, const float* __restrict__ w_dw,
    const float* __restrict__ w_pw, float* __restrict__ agg,
    __nv_bfloat16* __restrict__ oth, __nv_bfloat16* __restrict__ otl) {
  extern __shared__ float sm[];
  const int bx = blockIdx.x;
  const int tid = threadIdx.x;

  if (bx < 256) {
    // -------- attention role: head bh = bx, heads 0..63 of each batch -----
    const int b = bx >> 6;
    const int h = bx & 63;
    const float* base = qkv + (size_t)(b * 1536 + h * 24) * 4096;
    attn_head_body(base, b, h, sm, oth, otl);
    return;
  }

  // -------- dwpw role --------
  const int idx = bx - 256;
  const int g = idx % 192;
  const int rb = idx / 192;        // 0..15
  const int r0 = (rb & 3) * 16;
  const int b = rb >> 2;

  float* tile = sm;                // [8][20][68]
  float* wd = sm + 10880;          // [8][25]
  float* wp = sm + 11080;          // [64]

  if (tid < 200) {
    int i = tid / 25, t = tid % 25;
    wd[i * 25 + t] = w_dw[(size_t)(g * 8 + i) * 25 + t];
  }
  if (tid < 64) wp[tid] = w_pw[(size_t)g * 64 + tid];

  const float* src = qkv + (size_t)(b * 1536 + g * 8) * 4096;
  for (int e = tid; e < 8 * 20 * 68; e += 256) {
    int i = e / (20 * 68);
    int rem = e - i * (20 * 68);
    int ry = rem / 68;
    int rx = rem - ry * 68;
    int gy = r0 + ry - 2;
    int gx = rx - 2;
    float v = 0.f;
    if (gy >= 0 && gy < 64 && gx >= 0 && gx < 64)
      v = src[(size_t)i * 4096 + gy * 64 + gx];
    tile[i * 1360 + ry * 68 + rx] = v;
  }
  __syncthreads();

  const int px = tid & 63;
  const int py0 = (tid >> 6) * 4;
  float dwv[4][8];
#pragma unroll
  for (int i = 0; i < 8; i++) {
    float win[8][5];
#pragma unroll
    for (int r = 0; r < 8; r++)
#pragma unroll
      for (int c = 0; c < 5; c++)
        win[r][c] = tile[i * 1360 + (py0 + r) * 68 + px + c];
#pragma unroll
    for (int p = 0; p < 4; p++) {
      float s = 0.f;
#pragma unroll
      for (int ky = 0; ky < 5; ky++)
#pragma unroll
        for (int kx = 0; kx < 5; kx++)
          s += win[p + ky][kx] * wd[i * 25 + ky * 5 + kx];
      dwv[p][i] = s;
    }
  }

  float* dst = agg + (size_t)(b * 1536 + g * 8) * 4096;
#pragma unroll
  for (int o = 0; o < 8; o++) {
#pragma unroll
    for (int p = 0; p < 4; p++) {
      float a = 0.f;
#pragma unroll
      for (int i = 0; i < 8; i++) a += wp[o * 8 + i] * dwv[p][i];
      dst[(size_t)o * 4096 + (r0 + py0 + p) * 64 + px] = a;
    }
  }
}

// ---------------------------------------------------------------------------
// Attention for agg heads 64..127 (reads agg). 256 blocks.
// ---------------------------------------------------------------------------
__global__ __launch_bounds__(256) void attn_agg_kernel(
    const float* __restrict__ agg,
    __nv_bfloat16* __restrict__ oth, __nv_bfloat16* __restrict__ otl) {
  __shared__ float svk[72];
  const int bh = blockIdx.x;
  const int b = bh >> 6;
  const int hp = bh & 63;
  const float* base = agg + (size_t)(b * 1536 + hp * 24) * 4096;
  attn_head_body(base, b, hp + 64, svk, oth, otl);
}

// ---------------------------------------------------------------------------
extern "C" void kernel_launch(void* const* d_in, const int* in_sizes, int n_in,
                              void* d_out, int out_size) {
  const float* x      = (const float*)d_in[0];
  const float* w_qkv  = (const float*)d_in[1];
  const float* w_dw   = (const float*)d_in[2];
  const float* w_pw   = (const float*)d_in[3];
  const float* w_proj = (const float*)d_in[4];
  float* out = (float*)d_out;

  float *qkv, *agg;
  __nv_bfloat16 *xth, *xtl, *ath, *atl, *wqh, *wql, *wph, *wpl;
  cudaGetSymbolAddress((void**)&qkv, g_qkv);
  cudaGetSymbolAddress((void**)&agg, g_agg);
  cudaGetSymbolAddress((void**)&xth, g_xt_h);
  cudaGetSymbolAddress((void**)&xtl, g_xt_l);
  cudaGetSymbolAddress((void**)&ath, g_at_h);
  cudaGetSymbolAddress((void**)&atl, g_at_l);
  cudaGetSymbolAddress((void**)&wqh, g_wq_h);
  cudaGetSymbolAddress((void**)&wql, g_wq_l);
  cudaGetSymbolAddress((void**)&wph, g_wp_h);
  cudaGetSymbolAddress((void**)&wpl, g_wp_l);

  cudaFuncSetAttribute(gemm_hmma<false>,
                       cudaFuncAttributeMaxDynamicSharedMemorySize,
                       GEMM_SMEM_BYTES);
  cudaFuncSetAttribute(gemm_hmma<true>,
                       cudaFuncAttributeMaxDynamicSharedMemorySize,
                       GEMM_SMEM_BYTES);
  cudaFuncSetAttribute(dwpw_attnq_kernel,
                       cudaFuncAttributeMaxDynamicSharedMemorySize,
                       MERGED_SMEM_BYTES);

  // weight splits (tiny)
  split_bf16<<<(1536 * 512 + 255) / 256, 256>>>(w_qkv, wqh, wql, 1536 * 512);
  split_bf16<<<(512 * 1024 + 255) / 256, 256>>>(w_proj, wph, wpl, 512 * 1024);
  // x -> transposed bf16 split
  transpose_split<<<dim3(128, 16, 4), dim3(32, 8)>>>(x, xth, xtl, 512);
  // 1) qkv = w_qkv @ x  (HMMA bf16x3)
  gemm_hmma<false><<<dim3(12, 256), 256, GEMM_SMEM_BYTES>>>(
      wqh, wql, xth, xtl, nullptr, qkv, 1536, 512);
  // 2) merged: attention heads 0..63 (blocks 0-255) + dwpw (blocks 256-3327)
  dwpw_attnq_kernel<<<3328, 256, MERGED_SMEM_BYTES>>>(
      qkv, w_dw, w_pw, agg, ath, atl);
  // 3) attention heads 64..127 (reads agg)
  attn_agg_kernel<<<256, 256>>>(agg, ath, atl);
  // 4) out = x + w_proj @ attn  (HMMA bf16x3 + residual)
  gemm_hmma<true><<<dim3(4, 256), 256, GEMM_SMEM_BYTES>>>(
      wph, wpl, ath, atl, x, out, 512, 1024);
}

// round 14
// speedup vs baseline: 1.4779x; 1.1594x over previous
#include <cuda_runtime.h>
#include <cuda_bf16.h>
#include <cstdint>

#define EPS 1e-15f

// ---------------- scratch buffers (no runtime allocation allowed) ----------
__device__ float g_qkv[(size_t)4 * 1536 * 4096];          // fp32 qkv
__device__ float g_agg[(size_t)4 * 1536 * 4096];          // fp32 agg
__device__ __nv_bfloat16 g_xt_h[(size_t)4 * 512 * 4096];  // x split hi (k-major)
__device__ __nv_bfloat16 g_xt_l[(size_t)4 * 512 * 4096];  // x split lo
__device__ __nv_bfloat16 g_at_h[(size_t)4 * 1024 * 4096]; // attn out hi (k-major)
__device__ __nv_bfloat16 g_at_l[(size_t)4 * 1024 * 4096]; // attn out lo
__device__ __nv_bfloat16 g_wq_h[1536 * 512];
__device__ __nv_bfloat16 g_wq_l[1536 * 512];
__device__ __nv_bfloat16 g_wp_h[512 * 1024];
__device__ __nv_bfloat16 g_wp_l[512 * 1024];

// ---------------- PTX helpers (base-target-safe: HMMA/ldmatrix/cp.async) ----
__device__ __forceinline__ uint32_t smem_u32(const void* p) {
  uint32_t a;
  asm("{ .reg .u64 t; cvta.to.shared.u64 t, %1; cvt.u32.u64 %0, t; }"
      : "=r"(a) : "l"(p));
  return a;
}

__device__ __forceinline__ void cp_async16(uint32_t saddr, const void* gptr) {
  asm volatile("cp.async.cg.shared.global [%0], [%1], 16;" ::
               "r"(saddr), "l"(gptr));
}
__device__ __forceinline__ void cp_commit() {
  asm volatile("cp.async.commit_group;");
}
__device__ __forceinline__ void cp_wait_all() {
  asm volatile("cp.async.wait_group 0;");
}

__device__ __forceinline__ void ldsm4(uint32_t* r, uint32_t addr) {
  asm volatile("ldmatrix.sync.aligned.m8n8.x4.shared.b16 {%0,%1,%2,%3}, [%4];"
               : "=r"(r[0]), "=r"(r[1]), "=r"(r[2]), "=r"(r[3]) : "r"(addr));
}
__device__ __forceinline__ void ldsm4t(uint32_t* r, uint32_t addr) {
  asm volatile(
      "ldmatrix.sync.aligned.m8n8.x4.trans.shared.b16 {%0,%1,%2,%3}, [%4];"
      : "=r"(r[0]), "=r"(r[1]), "=r"(r[2]), "=r"(r[3]) : "r"(addr));
}

__device__ __forceinline__ void mma_bf16(float* d, const uint32_t* a,
                                         const uint32_t b0, const uint32_t b1) {
  asm volatile(
      "mma.sync.aligned.m16n8k16.row.col.f32.bf16.bf16.f32 "
      "{%0,%1,%2,%3}, {%4,%5,%6,%7}, {%8,%9}, {%0,%1,%2,%3};"
      : "+f"(d[0]), "+f"(d[1]), "+f"(d[2]), "+f"(d[3])
      : "r"(a[0]), "r"(a[1]), "r"(a[2]), "r"(a[3]), "r"(b0), "r"(b1));
}

// ---------------------------------------------------------------------------
// bf16x3 split GEMM on HMMA (mma.sync m16n8k16).
// C[b] (M x 4096 fp32) = A (M x K) * B[b], A = Ah+Al row-major [M][K],
// B = Bh+Bl K-MAJOR [K][4096] (n contiguous)  ->  ldmatrix.trans for B.
// product = Ah*Bh + Ah*Bl + Al*Bh (fp32 accumulate).
// CTA tile 128x64, K-chunk 64, double-buffered cp.async smem, 2 CTAs/SM.
// 8 warps: 4 (M) x 2 (N); warp tile 32x32. One __syncthreads per chunk.
// ---------------------------------------------------------------------------
#define STAGE_BYTES 49152           // Ah 16K + Al 16K + Bh 8K + Bl 8K
#define GEMM_SMEM_BYTES (2 * STAGE_BYTES)

template <bool RES>
__global__ void __launch_bounds__(256, 2) gemm_hmma(
    const __nv_bfloat16* __restrict__ Ah, const __nv_bfloat16* __restrict__ Al,
    const __nv_bfloat16* __restrict__ Bh, const __nv_bfloat16* __restrict__ Bl,
    const float* __restrict__ Res, float* __restrict__ C, int M, int K) {
  extern __shared__ char smem[];
  const uint32_t sbase = smem_u32(smem);

  const int tid = threadIdx.x;
  const int warp = tid >> 5;
  const int lane = tid & 31;
  const int wm = warp >> 1;        // 0..3 (M)
  const int wn = warp & 1;         // 0..1 (N)
  const int m0 = blockIdx.x * 128;
  const int by = blockIdx.y;
  const int batch = by >> 6;
  const int n0 = (by & 63) * 64;
  const int NB = 4096;

  const __nv_bfloat16* Bhb = Bh + (size_t)batch * NB * K;
  const __nv_bfloat16* Blb = Bl + (size_t)batch * NB * K;

  float acc[2][4][4];
#pragma unroll
  for (int i = 0; i < 2; i++)
#pragma unroll
    for (int j = 0; j < 4; j++)
#pragma unroll
      for (int r = 0; r < 4; r++) acc[i][j][r] = 0.f;

  const int nch = K >> 6;

  // ---- stage loader: Ah/Al 128 m-rows, Bh/Bl 64 k-rows; 128B rows --------
  const int lrow0 = tid >> 3;      // 0..31
  const int lc = tid & 7;          // 16B chunk 0..7
  auto load_stage = [&](int ch, int s) {
    const int k0 = ch << 6;
    const uint32_t sb = sbase + (uint32_t)s * STAGE_BYTES;
#pragma unroll
    for (int i = 0; i < 4; i++) {
      const int row = lrow0 + 32 * i;
      const uint32_t soff =
          (uint32_t)row * 128u + (uint32_t)((lc ^ (row & 7)) << 4);
      const size_t ga = (size_t)(m0 + row) * K + k0 + lc * 8;
      cp_async16(sb + 0u + soff, Ah + ga);
      cp_async16(sb + 16384u + soff, Al + ga);
    }
#pragma unroll
    for (int i = 0; i < 2; i++) {
      const int row = lrow0 + 32 * i;          // k-row within chunk
      const uint32_t soff =
          (uint32_t)row * 128u + (uint32_t)((lc ^ (row & 7)) << 4);
      const size_t gb = (size_t)(k0 + row) * NB + n0 + lc * 8;
      cp_async16(sb + 32768u + soff, Bhb + gb);
      cp_async16(sb + 40960u + soff, Blb + gb);
    }
    cp_commit();
  };

  load_stage(0, 0);

  const int lr = lane & 15;
  const int kh = lane >> 4;
  const int arow0 = wm * 32 + lr;         // + mt*16  (m-rows for A)
  // B (trans): row = s*16 + lr (k-row), col-octet = wn*4 + nt2*2 + kh
  const int bcol0 = wn * 4 + kh;          // + nt2*2

  for (int ch = 0; ch < nch; ch++) {
    cp_wait_all();
    __syncthreads();
    if (ch + 1 < nch) load_stage(ch + 1, (ch + 1) & 1);

    const uint32_t sb = sbase + (uint32_t)(ch & 1) * STAGE_BYTES;
    const uint32_t sAh = sb, sAl = sb + 16384u;
    const uint32_t sBh = sb + 32768u, sBl = sb + 40960u;

    uint32_t ah[2][2][4], bh[2][2][4];   // double-buffered across s
    uint32_t al[2][4], bl[2][4];         // single-buffered (loaded per s)

    // preload s=0 primary operands
#pragma unroll
    for (int mt = 0; mt < 2; mt++) {
      const int row = arow0 + mt * 16;
      ldsm4(ah[0][mt],
            sAh + (uint32_t)row * 128u + (uint32_t)((kh ^ (row & 7)) << 4));
    }
#pragma unroll
    for (int nt2 = 0; nt2 < 2; nt2++) {
      const int row = lr;                 // s=0
      const int col = bcol0 + nt2 * 2;
      ldsm4t(bh[0][nt2],
             sBh + (uint32_t)row * 128u + (uint32_t)((col ^ (row & 7)) << 4));
    }

#pragma unroll
    for (int s = 0; s < 4; s++) {
      const int cur = s & 1, nxt = cur ^ 1;
      const int chunk = 2 * s + kh;       // A 16B chunk
      const int brow = s * 16 + lr;       // B k-row
      // secondary operands for this s (latency covered by term1 below)
#pragma unroll
      for (int nt2 = 0; nt2 < 2; nt2++) {
        const int col = bcol0 + nt2 * 2;
        ldsm4t(bl[nt2], sBl + (uint32_t)brow * 128u +
                            (uint32_t)((col ^ (brow & 7)) << 4));
      }
#pragma unroll
      for (int mt = 0; mt < 2; mt++) {
        const int row = arow0 + mt * 16;
        ldsm4(al[mt], sAl + (uint32_t)row * 128u +
                          (uint32_t)((chunk ^ (row & 7)) << 4));
      }
      // term1: ah x bh   (b frags: octet = nt&1 -> regs {2o, 2o+1})
#pragma unroll
      for (int mt = 0; mt < 2; mt++)
#pragma unroll
        for (int nt = 0; nt < 4; nt++)
          mma_bf16(acc[mt][nt], ah[cur][mt],
                   bh[cur][nt >> 1][(nt & 1) * 2],
                   bh[cur][nt >> 1][(nt & 1) * 2 + 1]);
      // prefetch next s primary operands (covered by term2+term3)
      if (s < 3) {
        const int nchunk = chunk + 2;
        const int nbrow = brow + 16;
#pragma unroll
        for (int mt = 0; mt < 2; mt++) {
          const int row = arow0 + mt * 16;
          ldsm4(ah[nxt][mt], sAh + (uint32_t)row * 128u +
                                 (uint32_t)((nchunk ^ (row & 7)) << 4));
        }
#pragma unroll
        for (int nt2 = 0; nt2 < 2; nt2++) {
          const int col = bcol0 + nt2 * 2;
          ldsm4t(bh[nxt][nt2], sBh + (uint32_t)nbrow * 128u +
                                   (uint32_t)((col ^ (nbrow & 7)) << 4));
        }
      }
      // term2: ah x bl
#pragma unroll
      for (int mt = 0; mt < 2; mt++)
#pragma unroll
        for (int nt = 0; nt < 4; nt++)
          mma_bf16(acc[mt][nt], ah[cur][mt],
                   bl[nt >> 1][(nt & 1) * 2], bl[nt >> 1][(nt & 1) * 2 + 1]);
      // term3: al x bh
#pragma unroll
      for (int mt = 0; mt < 2; mt++)
#pragma unroll
        for (int nt = 0; nt < 4; nt++)
          mma_bf16(acc[mt][nt], al[mt],
                   bh[cur][nt >> 1][(nt & 1) * 2],
                   bh[cur][nt >> 1][(nt & 1) * 2 + 1]);
    }
  }

  // ---- epilogue: write 32x32 warp region, fp32, optional residual ----
  const int qrow = lane >> 2;
  const int qcol = (lane & 3) * 2;
#pragma unroll
  for (int mt = 0; mt < 2; mt++) {
#pragma unroll
    for (int half = 0; half < 2; half++) {
      const int grow = m0 + wm * 32 + mt * 16 + qrow + half * 8;
      float* crow = C + ((size_t)batch * M + grow) * NB;
      const float* rrow =
          RES ? (Res + ((size_t)batch * M + grow) * NB) : nullptr;
#pragma unroll
      for (int nt = 0; nt < 4; nt++) {
        const int gcol = n0 + wn * 32 + nt * 8 + qcol;
        float2 v = make_float2(acc[mt][nt][half * 2],
                               acc[mt][nt][half * 2 + 1]);
        if (RES) {
          float2 r = *(const float2*)(rrow + gcol);
          v.x += r.x; v.y += r.y;
        }
        *(float2*)(crow + gcol) = v;
      }
    }
  }
}

// ---------------------------------------------------------------------------
// Vectorized split fp32 -> (bf16 hi, bf16 lo). n must be divisible by 4.
// ---------------------------------------------------------------------------
__global__ void split_bf16_v4(const float4* __restrict__ w,
                              uint2* __restrict__ h, uint2* __restrict__ l,
                              int n4) {
  int i = blockIdx.x * blockDim.x + threadIdx.x;
  if (i < n4) {
    float4 f = w[i];
    __nv_bfloat16 h0 = __float2bfloat16(f.x);
    __nv_bfloat16 h1 = __float2bfloat16(f.y);
    __nv_bfloat16 h2 = __float2bfloat16(f.z);
    __nv_bfloat16 h3 = __float2bfloat16(f.w);
    uint2 uh, ul;
    uh.x = (uint32_t)__bfloat16_as_ushort(h0) |
           ((uint32_t)__bfloat16_as_ushort(h1) << 16);
    uh.y = (uint32_t)__bfloat16_as_ushort(h2) |
           ((uint32_t)__bfloat16_as_ushort(h3) << 16);
    ul.x = (uint32_t)__bfloat16_as_ushort(
               __float2bfloat16(f.x - __bfloat162float(h0))) |
           ((uint32_t)__bfloat16_as_ushort(
                __float2bfloat16(f.y - __bfloat162float(h1))) << 16);
    ul.y = (uint32_t)__bfloat16_as_ushort(
               __float2bfloat16(f.z - __bfloat162float(h2))) |
           ((uint32_t)__bfloat16_as_ushort(
                __float2bfloat16(f.w - __bfloat162float(h3))) << 16);
    h[i] = uh;
    l[i] = ul;
  }
}

// ---------------------------------------------------------------------------
// Fused depthwise 5x5 (pad 2) + grouped 1x1 (192 groups, 8 in -> 8 out).
// ---------------------------------------------------------------------------
__global__ __launch_bounds__(256) void dwpw_kernel(
    const float* __restrict__ qkv, const float* __restrict__ w_dw,
    const float* __restrict__ w_pw, float* __restrict__ agg) {
  const int g = blockIdx.x;
  const int r0 = blockIdx.y * 16;
  const int b = blockIdx.z;
  const int tid = threadIdx.x;

  __shared__ float tile[8][20][68];
  __shared__ float wd[8][25];
  __shared__ float wp[64];

  if (tid < 200) {
    int i = tid / 25, t = tid % 25;
    wd[i][t] = w_dw[(size_t)(g * 8 + i) * 25 + t];
  }
  if (tid < 64) wp[tid] = w_pw[(size_t)g * 64 + tid];

  const float* src = qkv + (size_t)(b * 1536 + g * 8) * 4096;
  for (int e = tid; e < 8 * 20 * 68; e += 256) {
    int i = e / (20 * 68);
    int rem = e - i * (20 * 68);
    int ry = rem / 68;
    int rx = rem - ry * 68;
    int gy = r0 + ry - 2;
    int gx = rx - 2;
    float v = 0.f;
    if (gy >= 0 && gy < 64 && gx >= 0 && gx < 64)
      v = src[(size_t)i * 4096 + gy * 64 + gx];
    tile[i][ry][rx] = v;
  }
  __syncthreads();

  const int px = tid & 63;
  const int py0 = (tid >> 6) * 4;
  float dwv[4][8];
#pragma unroll
  for (int i = 0; i < 8; i++) {
    float win[8][5];
#pragma unroll
    for (int r = 0; r < 8; r++)
#pragma unroll
      for (int c = 0; c < 5; c++) win[r][c] = tile[i][py0 + r][px + c];
#pragma unroll
    for (int p = 0; p < 4; p++) {
      float s = 0.f;
#pragma unroll
      for (int ky = 0; ky < 5; ky++)
#pragma unroll
        for (int kx = 0; kx < 5; kx++)
          s += win[p + ky][kx] * wd[i][ky * 5 + kx];
      dwv[p][i] = s;
    }
  }

  float* dst = agg + (size_t)(b * 1536 + g * 8) * 4096;
#pragma unroll
  for (int o = 0; o < 8; o++) {
#pragma unroll
    for (int p = 0; p < 4; p++) {
      float a = 0.f;
#pragma unroll
      for (int i = 0; i < 8; i++) a += wp[o * 8 + i] * dwv[p][i];
      dst[(size_t)o * 4096 + (r0 + py0 + p) * 64 + px] = a;
    }
  }
}

// ---------------------------------------------------------------------------
// Linear attention per head (all 128 heads; 512 blocks). Writes K-MAJOR
// bf16 hi/lo output: at[(b*1024 + h*8 + d)][n] — fully coalesced stores.
// ---------------------------------------------------------------------------
__global__ __launch_bounds__(256) void attn_kernel(
    const float* __restrict__ qkv, const float* __restrict__ agg,
    __nv_bfloat16* __restrict__ oth, __nv_bfloat16* __restrict__ otl) {
  const int bh = blockIdx.x;
  const int b = bh >> 7;
  const int h = bh & 127;
  const float* base = (h < 64)
      ? qkv + (size_t)(b * 1536 + h * 24) * 4096
      : agg + (size_t)(b * 1536 + (h - 64) * 24) * 4096;
  const float4* qp4 = (const float4*)base;
  const float4* kp4 = (const float4*)(base + (size_t)8 * 4096);
  const float4* vp4 = (const float4*)(base + (size_t)16 * 4096);

  __shared__ float svk[72];
  const int tid = threadIdx.x;
  if (tid < 72) svk[tid] = 0.f;
  __syncthreads();

  float a[72];
#pragma unroll
  for (int t = 0; t < 72; t++) a[t] = 0.f;

  for (int n4 = tid; n4 < 1024; n4 += 256) {
    float4 kv4[8], vv4[8];
#pragma unroll
    for (int e = 0; e < 8; e++) {
      float4 f = kp4[e * 1024 + n4];
      kv4[e] = make_float4(fmaxf(f.x, 0.f), fmaxf(f.y, 0.f),
                           fmaxf(f.z, 0.f), fmaxf(f.w, 0.f));
    }
#pragma unroll
    for (int d = 0; d < 8; d++) vv4[d] = vp4[d * 1024 + n4];
#pragma unroll
    for (int d = 0; d < 8; d++)
#pragma unroll
      for (int e = 0; e < 8; e++)
        a[d * 8 + e] += vv4[d].x * kv4[e].x + vv4[d].y * kv4[e].y +
                        vv4[d].z * kv4[e].z + vv4[d].w * kv4[e].w;
#pragma unroll
    for (int e = 0; e < 8; e++)
      a[64 + e] += kv4[e].x + kv4[e].y + kv4[e].z + kv4[e].w;
  }

#pragma unroll
  for (int t = 0; t < 72; t++) {
    float s = a[t];
    s += __shfl_down_sync(0xffffffffu, s, 16);
    s += __shfl_down_sync(0xffffffffu, s, 8);
    s += __shfl_down_sync(0xffffffffu, s, 4);
    s += __shfl_down_sync(0xffffffffu, s, 2);
    s += __shfl_down_sync(0xffffffffu, s, 1);
    if ((tid & 31) == 0) atomicAdd(&svk[t], s);
  }
  __syncthreads();

  float vk[72];
#pragma unroll
  for (int t = 0; t < 72; t++) vk[t] = svk[t];

  // phase 2: outputs packed per-d across 4 consecutive n -> coalesced uint2
  const size_t orow0 = ((size_t)b * 1024 + (size_t)h * 8);
  for (int n4 = tid; n4 < 1024; n4 += 256) {
    float qs[4][8];
#pragma unroll
    for (int e = 0; e < 8; e++) {
      float4 f = qp4[e * 1024 + n4];
      qs[0][e] = fmaxf(f.x, 0.f);
      qs[1][e] = fmaxf(f.y, 0.f);
      qs[2][e] = fmaxf(f.z, 0.f);
      qs[3][e] = fmaxf(f.w, 0.f);
    }
    float rden[4];
#pragma unroll
    for (int sub = 0; sub < 4; sub++) {
      float den = EPS;
#pragma unroll
      for (int e = 0; e < 8; e++) den += vk[64 + e] * qs[sub][e];
      rden[sub] = 1.0f / den;
    }
#pragma unroll
    for (int d = 0; d < 8; d++) {
      unsigned short hh[4], ll[4];
#pragma unroll
      for (int sub = 0; sub < 4; sub++) {
        float num = 0.f;
#pragma unroll
        for (int e = 0; e < 8; e++) num += vk[d * 8 + e] * qs[sub][e];
        float v = num * rden[sub];
        __nv_bfloat16 hb = __float2bfloat16(v);
        hh[sub] = __bfloat16_as_ushort(hb);
        ll[sub] = __bfloat16_as_ushort(
            __float2bfloat16(v - __bfloat162float(hb)));
      }
      const size_t o = (orow0 + d) * 4096 + (size_t)n4 * 4;
      uint2 uh, ul;
      uh.x = (uint32_t)hh[0] | ((uint32_t)hh[1] << 16);
      uh.y = (uint32_t)hh[2] | ((uint32_t)hh[3] << 16);
      ul.x = (uint32_t)ll[0] | ((uint32_t)ll[1] << 16);
      ul.y = (uint32_t)ll[2] | ((uint32_t)ll[3] << 16);
      *(uint2*)(oth + o) = uh;
      *(uint2*)(otl + o) = ul;
    }
  }
}

// ---------------------------------------------------------------------------
extern "C" void kernel_launch(void* const* d_in, const int* in_sizes, int n_in,
                              void* d_out, int out_size) {
  const float* x      = (const float*)d_in[0];
  const float* w_qkv  = (const float*)d_in[1];
  const float* w_dw   = (const float*)d_in[2];
  const float* w_pw   = (const float*)d_in[3];
  const float* w_proj = (const float*)d_in[4];
  float* out = (float*)d_out;

  float *qkv, *agg;
  __nv_bfloat16 *xth, *xtl, *ath, *atl, *wqh, *wql, *wph, *wpl;
  cudaGetSymbolAddress((void**)&qkv, g_qkv);
  cudaGetSymbolAddress((void**)&agg, g_agg);
  cudaGetSymbolAddress((void**)&xth, g_xt_h);
  cudaGetSymbolAddress((void**)&xtl, g_xt_l);
  cudaGetSymbolAddress((void**)&ath, g_at_h);
  cudaGetSymbolAddress((void**)&atl, g_at_l);
  cudaGetSymbolAddress((void**)&wqh, g_wq_h);
  cudaGetSymbolAddress((void**)&wql, g_wq_l);
  cudaGetSymbolAddress((void**)&wph, g_wp_h);
  cudaGetSymbolAddress((void**)&wpl, g_wp_l);

  cudaFuncSetAttribute(gemm_hmma<false>,
                       cudaFuncAttributeMaxDynamicSharedMemorySize,
                       GEMM_SMEM_BYTES);
  cudaFuncSetAttribute(gemm_hmma<true>,
                       cudaFuncAttributeMaxDynamicSharedMemorySize,
                       GEMM_SMEM_BYTES);

  // weight splits (A operands, row-major [M][K])
  split_bf16_v4<<<(1536 * 512 / 4 + 255) / 256, 256>>>(
      (const float4*)w_qkv, (uint2*)wqh, (uint2*)wql, 1536 * 512 / 4);
  split_bf16_v4<<<(512 * 1024 / 4 + 255) / 256, 256>>>(
      (const float4*)w_proj, (uint2*)wph, (uint2*)wpl, 512 * 1024 / 4);
  // x is already K-major [B][512][4096] -> pure streaming split (no transpose)
  split_bf16_v4<<<((int)(4 * 512 * 4096 / 4) + 255) / 256, 256>>>(
      (const float4*)x, (uint2*)xth, (uint2*)xtl, 4 * 512 * 4096 / 4);
  // 1) qkv = w_qkv @ x  (HMMA bf16x3, B k-major via ldsm.trans)
  gemm_hmma<false><<<dim3(12, 256), 256, GEMM_SMEM_BYTES>>>(
      wqh, wql, xth, xtl, nullptr, qkv, 1536, 512);
  // 2) agg = grouped_pw(depthwise5x5(qkv))
  dwpw_kernel<<<dim3(192, 4, 4), 256>>>(qkv, w_dw, w_pw, agg);
  // 3) linear attention -> K-major bf16 split (coalesced stores)
  attn_kernel<<<512, 256>>>(qkv, agg, ath, atl);
  // 4) out = x + w_proj @ attn  (HMMA bf16x3 + residual)
  gemm_hmma<true><<<dim3(4, 256), 256, GEMM_SMEM_BYTES>>>(
      wph, wpl, ath, atl, x, out, 512, 1024);
}